// round 11
// baseline (speedup 1.0000x reference)
#include <cuda_runtime.h>
#include <cstdint>

// Problem constants
#define N_IMG   64
#define C_IN    64
#define H_IN    128
#define W_IN    128
#define KH      3
#define KW      3
#define OH      126
#define OW      126

// Tiling: 64x64 output tile per block (best traffic/smem ratio from R5)
#define TILE_W  64
#define TILE_H  64
#define SM_W    68            // padded width: 17 float4 chunks per row
#define SM_H    66            // TILE_H + KH - 1
#define THREADS 256
#define STAGES  3
#define KER_ELEMS (C_IN * KH * KW)   // 576

#define STAGE_ELEMS (SM_H * SM_W)    // 4488 floats = 17952 B
#define CHUNKS_PER_ROW 17
#define TOTAL_CHUNKS   (SM_H * CHUNKS_PER_ROW)   // 1122
#define CHUNK_ITERS    ((TOTAL_CHUNKS + THREADS - 1) / THREADS)  // 5

// dynamic smem: 3 stages + kernels = 3*17952 + 2304 = 56160 B
#define SMEM_BYTES (STAGES * STAGE_ELEMS * 4 + KER_ELEMS * 4)

__device__ __forceinline__ uint32_t smem_u32(const void* p) {
    uint32_t a;
    asm("{ .reg .u64 t; cvta.to.shared.u64 t, %1; cvt.u32.u64 %0, t; }" : "=r"(a) : "l"(p));
    return a;
}
__device__ __forceinline__ void cp_async16(uint32_t smem_addr, const void* gptr) {
    asm volatile("cp.async.cg.shared.global [%0], [%1], 16;\n" :: "r"(smem_addr), "l"(gptr));
}
__device__ __forceinline__ void cp_commit() {
    asm volatile("cp.async.commit_group;\n" ::: "memory");
}
__device__ __forceinline__ void cp_wait_1() {
    asm volatile("cp.async.wait_group 1;\n" ::: "memory");
}

__global__ __launch_bounds__(THREADS, 2)
void imagewise_conv2d_kernel(const float* __restrict__ images,
                             const float* __restrict__ kernels,
                             float* __restrict__ out)
{
    extern __shared__ float smem[];
    float* s_stage[STAGES];
#pragma unroll
    for (int s = 0; s < STAGES; ++s) s_stage[s] = smem + s * STAGE_ELEMS;
    float* s_ker = smem + STAGES * STAGE_ELEMS;

    const int tid = threadIdx.x;
    const int n   = blockIdx.z;
    const int ox0 = blockIdx.x * TILE_W;
    const int oy0 = blockIdx.y * TILE_H;

    // Stage this sample's full kernel stack once (published by first barrier)
    for (int i = tid; i < KER_ELEMS; i += THREADS) {
        s_ker[i] = kernels[n * KER_ELEMS + i];
    }

    const float* img_n = images + (size_t)n * C_IN * H_IN * W_IN;

    // ---- Per-thread cp.async chunk addresses (channel-invariant) ----
    // Clamped chunks fill only smem cells consumed by never-stored outputs.
    int      g_off[CHUNK_ITERS];
    uint32_t s_off[CHUNK_ITERS];
    bool     valid[CHUNK_ITERS];
#pragma unroll
    for (int it = 0; it < CHUNK_ITERS; ++it) {
        int j = tid + it * THREADS;
        valid[it] = (j < TOTAL_CHUNKS);
        if (!valid[it]) j = TOTAL_CHUNKS - 1;
        int row = j / CHUNKS_PER_ROW;
        int k   = j - row * CHUNKS_PER_ROW;
        int gy  = oy0 + row; if (gy > H_IN - 1) gy = H_IN - 1;
        int gx  = ox0 + 4 * k; if (gx > W_IN - 4) gx = W_IN - 4;
        g_off[it] = gy * W_IN + gx;
        s_off[it] = (uint32_t)((row * SM_W + 4 * k) * sizeof(float));
    }
    uint32_t s_base[STAGES];
#pragma unroll
    for (int s = 0; s < STAGES; ++s) s_base[s] = smem_u32(s_stage[s]);

    // ---- Compute mapping: 4 cols x 4 rows per thread (9 B smem / output) ----
    const int tx   = tid & 15;       // cols 4tx..4tx+3
    const int tyg  = tid >> 4;       // rows 4tyg..4tyg+3
    const int col0 = 4 * tx;
    const int row0 = 4 * tyg;

    float acc[4][4];
#pragma unroll
    for (int o = 0; o < 4; ++o)
#pragma unroll
        for (int cc = 0; cc < 4; ++cc) acc[o][cc] = 0.0f;

    // ---- Prologue: prefetch channels 0 and 1 ----
#pragma unroll
    for (int s = 0; s < STAGES - 1; ++s) {
        const float* img_c = img_n + (size_t)s * H_IN * W_IN;
#pragma unroll
        for (int it = 0; it < CHUNK_ITERS; ++it)
            if (valid[it]) cp_async16(s_base[s] + s_off[it], img_c + g_off[it]);
        cp_commit();
    }

    // ---- Main loop: depth-3 pipeline, ONE barrier per channel ----
    int cur = 0;   // buffer holding channel c
    for (int c = 0; c < C_IN; ++c) {
        cp_wait_1();       // group c complete (<=1 group still in flight)
        __syncthreads();   // publish stage c; all threads done reading buf[(c-1)%3]

        // Prefetch channel c+2 into the buffer just freed
        {
            int cn  = c + STAGES - 1;
            int tgt = (cur == 0) ? (STAGES - 1) : (cur - 1);
            if (cn < C_IN) {
                const float* img_c = img_n + (size_t)cn * H_IN * W_IN;
#pragma unroll
                for (int it = 0; it < CHUNK_ITERS; ++it)
                    if (valid[it]) cp_async16(s_base[tgt] + s_off[it], img_c + g_off[it]);
            }
            cp_commit();   // empty tail groups keep the wait_group count aligned
        }

        // Channel c's 3x3 weights (broadcast LDS)
        const float w0 = s_ker[c * 9 + 0], w1 = s_ker[c * 9 + 1], w2 = s_ker[c * 9 + 2];
        const float w3 = s_ker[c * 9 + 3], w4 = s_ker[c * 9 + 4], w5 = s_ker[c * 9 + 5];
        const float w6 = s_ker[c * 9 + 6], w7 = s_ker[c * 9 + 7], w8 = s_ker[c * 9 + 8];

        const float* colp = s_stage[cur] + row0 * SM_W + col0;
#pragma unroll
        for (int r = 0; r < 4 + KH - 1; ++r) {   // 6 input rows -> 4 output rows
            float4 f4 = *(const float4*)(colp + r * SM_W);
            float2 f2 = *(const float2*)(colp + r * SM_W + 4);
            float x[6] = {f4.x, f4.y, f4.z, f4.w, f2.x, f2.y};
#pragma unroll
            for (int o = 0; o < 4; ++o) {
                int ky = r - o;
                if (ky >= 0 && ky < KH) {
                    float wa = (ky == 0) ? w0 : (ky == 1) ? w3 : w6;
                    float wb = (ky == 0) ? w1 : (ky == 1) ? w4 : w7;
                    float wc = (ky == 0) ? w2 : (ky == 1) ? w5 : w8;
#pragma unroll
                    for (int cc = 0; cc < 4; ++cc) {
                        acc[o][cc] = fmaf(x[cc + 0], wa,
                                     fmaf(x[cc + 1], wb,
                                     fmaf(x[cc + 2], wc, acc[o][cc])));
                    }
                }
            }
        }

        cur = (cur == STAGES - 1) ? 0 : cur + 1;
    }

    // ---- Store valid outputs ----
    float* out_n = out + (size_t)n * OH * OW;
#pragma unroll
    for (int o = 0; o < 4; ++o) {
        int gy = oy0 + row0 + o;
        if (gy < OH) {
#pragma unroll
            for (int cc = 0; cc < 4; ++cc) {
                int gx = ox0 + col0 + cc;
                if (gx < OW) {
                    out_n[gy * OW + gx] = acc[o][cc];
                }
            }
        }
    }
}

extern "C" void kernel_launch(void* const* d_in, const int* in_sizes, int n_in,
                              void* d_out, int out_size)
{
    const float* images  = (const float*)d_in[0];
    const float* kernels = (const float*)d_in[1];
    float* out = (float*)d_out;

    // >48KB dynamic smem requires opt-in (idempotent; capture-safe host call)
    cudaFuncSetAttribute(imagewise_conv2d_kernel,
                         cudaFuncAttributeMaxDynamicSharedMemorySize, SMEM_BYTES);

    dim3 grid((OW + TILE_W - 1) / TILE_W,   // 2
              (OH + TILE_H - 1) / TILE_H,   // 2
              N_IMG);                       // 64 -> 256 CTAs
    imagewise_conv2d_kernel<<<grid, THREADS, SMEM_BYTES>>>(images, kernels, out);
}

// round 15
// speedup vs baseline: 1.1251x; 1.1251x over previous
#include <cuda_runtime.h>
#include <cstdint>

// Problem constants
#define N_IMG   64
#define C_IN    64
#define H_IN    128
#define W_IN    128
#define KH      3
#define KW      3
#define OH      126
#define OW      126

// Tiling: full-width stripe, 128 wide x 16 tall per CTA (no x-halo)
#define TILE_H  16
#define Y_TILES 8              // ceil(126/16): 7 full + one 14-row tile
#define SM_W    132            // 128 cols + 4 pad floats
#define SM_H    18             // TILE_H + KH - 1
#define THREADS 256
#define KER_ELEMS (C_IN * KH * KW)   // 576

#define STAGE_ELEMS (SM_H * SM_W)    // 2376 floats = 9504 B
#define CHUNKS_PER_ROW 32            // 32 * 4 floats = 128 cols, exact
#define TOTAL_CHUNKS   (SM_H * CHUNKS_PER_ROW)   // 576
#define CHUNK_ITERS    ((TOTAL_CHUNKS + THREADS - 1) / THREADS)  // 3 (last partial)

__device__ __forceinline__ uint32_t smem_u32(const void* p) {
    uint32_t a;
    asm("{ .reg .u64 t; cvta.to.shared.u64 t, %1; cvt.u32.u64 %0, t; }" : "=r"(a) : "l"(p));
    return a;
}
__device__ __forceinline__ void cp_async16(uint32_t smem_addr, const void* gptr) {
    asm volatile("cp.async.cg.shared.global [%0], [%1], 16;\n" :: "r"(smem_addr), "l"(gptr));
}
__device__ __forceinline__ void cp_commit() {
    asm volatile("cp.async.commit_group;\n" ::: "memory");
}
__device__ __forceinline__ void cp_wait_1() {
    asm volatile("cp.async.wait_group 1;\n" ::: "memory");
}

__global__ __launch_bounds__(THREADS, 4)
void imagewise_conv2d_kernel(const float* __restrict__ images,
                             const float* __restrict__ kernels,
                             float* __restrict__ out)
{
    __shared__ float s_img[2][STAGE_ELEMS];   // 2 * 9504 = 19008 B
    __shared__ float s_ker[KER_ELEMS];        // 2304 B  -> 21312 B total

    const int tid = threadIdx.x;
    const int n   = blockIdx.y;            // image index
    const int y0  = blockIdx.x * TILE_H;   // first output row of this stripe

    // Stage this sample's full kernel stack once
    for (int i = tid; i < KER_ELEMS; i += THREADS) {
        s_ker[i] = kernels[n * KER_ELEMS + i];
    }

    const float* img_n = images + (size_t)n * C_IN * H_IN * W_IN;

    // ---- Per-thread cp.async chunk addresses (channel-invariant, no x clamp) ----
    int      g_off[CHUNK_ITERS];
    uint32_t s_off[CHUNK_ITERS];
    bool     valid[CHUNK_ITERS];
#pragma unroll
    for (int it = 0; it < CHUNK_ITERS; ++it) {
        int j = tid + it * THREADS;
        valid[it] = (j < TOTAL_CHUNKS);
        if (!valid[it]) j = TOTAL_CHUNKS - 1;
        int row = j >> 5;            // j / 32
        int k   = j & 31;
        int gy  = y0 + row; if (gy > H_IN - 1) gy = H_IN - 1;   // y clamp only
        g_off[it] = gy * W_IN + 4 * k;
        s_off[it] = (uint32_t)((row * SM_W + 4 * k) * sizeof(float));
    }
    const uint32_t s_base0 = smem_u32(&s_img[0][0]);
    const uint32_t s_base1 = smem_u32(&s_img[1][0]);

    // ---- Compute mapping: 2 cols x 4 rows per thread ----
    const int tx   = tid & 63;       // col group: cols 2tx, 2tx+1
    const int tyg  = tid >> 6;       // row group: rows 4tyg..4tyg+3
    const int col0 = 2 * tx;
    const int row0 = 4 * tyg;

    float acc[4][2];
#pragma unroll
    for (int o = 0; o < 4; ++o) { acc[o][0] = 0.0f; acc[o][1] = 0.0f; }

    // ---- Prologue: prefetch channel 0 into buf 0 ----
#pragma unroll
    for (int it = 0; it < CHUNK_ITERS; ++it)
        if (valid[it]) cp_async16(s_base0 + s_off[it], img_n + g_off[it]);
    cp_commit();

    // ---- Main loop: depth-2, R5-proven barrier pattern ----
    for (int c = 0; c < C_IN; ++c) {
        __syncthreads();   // all warps done reading buf[(c+1)&1] (compute c-1)

        // Prefetch next channel (wrap at end: harmless redundant load)
        {
            int cn = (c + 1) & (C_IN - 1);
            const float* img_c = img_n + (size_t)cn * H_IN * W_IN;
            uint32_t sb = ((c + 1) & 1) ? s_base1 : s_base0;
#pragma unroll
            for (int it = 0; it < CHUNK_ITERS; ++it)
                if (valid[it]) cp_async16(sb + s_off[it], img_c + g_off[it]);
            cp_commit();
        }

        cp_wait_1();       // channel c's group complete
        __syncthreads();   // publish to all warps

        const float* buf = s_img[c & 1];

        const float w0 = s_ker[c * 9 + 0], w1 = s_ker[c * 9 + 1], w2 = s_ker[c * 9 + 2];
        const float w3 = s_ker[c * 9 + 3], w4 = s_ker[c * 9 + 4], w5 = s_ker[c * 9 + 5];
        const float w6 = s_ker[c * 9 + 6], w7 = s_ker[c * 9 + 7], w8 = s_ker[c * 9 + 8];

        // 6 input rows feed 4 output rows.
        // col0 is only 8B-aligned (2*tx) -> use two LDS.64, NOT one LDS.128.
        const float* colp = buf + row0 * SM_W + col0;
#pragma unroll
        for (int r = 0; r < 4 + KH - 1; ++r) {
            float2 fa = *(const float2*)(colp + r * SM_W);       // cols col0, col0+1
            float2 fb = *(const float2*)(colp + r * SM_W + 2);   // cols col0+2, col0+3
            float x[4] = {fa.x, fa.y, fb.x, fb.y};
#pragma unroll
            for (int o = 0; o < 4; ++o) {
                int ky = r - o;
                if (ky >= 0 && ky < KH) {
                    float wa = (ky == 0) ? w0 : (ky == 1) ? w3 : w6;
                    float wb = (ky == 0) ? w1 : (ky == 1) ? w4 : w7;
                    float wc = (ky == 0) ? w2 : (ky == 1) ? w5 : w8;
                    acc[o][0] = fmaf(x[0], wa, fmaf(x[1], wb, fmaf(x[2], wc, acc[o][0])));
                    acc[o][1] = fmaf(x[1], wa, fmaf(x[2], wb, fmaf(x[3], wc, acc[o][1])));
                }
            }
        }
    }

    // ---- Store valid outputs (float2, 8B-aligned since col0 even) ----
    if (col0 <= OW - 2) {            // col0 = 126 -> both cols out of range
        float* out_n = out + (size_t)n * OH * OW;
#pragma unroll
        for (int o = 0; o < 4; ++o) {
            int gy = y0 + row0 + o;
            if (gy < OH) {
                *(float2*)(out_n + gy * OW + col0) = make_float2(acc[o][0], acc[o][1]);
            }
        }
    }
}

extern "C" void kernel_launch(void* const* d_in, const int* in_sizes, int n_in,
                              void* d_out, int out_size)
{
    const float* images  = (const float*)d_in[0];
    const float* kernels = (const float*)d_in[1];
    float* out = (float*)d_out;

    dim3 grid(Y_TILES, N_IMG);   // 8 x 64 = 512 CTAs
    imagewise_conv2d_kernel<<<grid, THREADS>>>(images, kernels, out);
}

// round 17
// speedup vs baseline: 1.2311x; 1.0942x over previous
#include <cuda_runtime.h>
#include <cstdint>

// Problem constants
#define N_IMG   64
#define C_IN    64
#define H_IN    128
#define W_IN    128
#define KH      3
#define KW      3
#define OH      126
#define OW      126

// Tiling: full-width stripe, 128 wide x 14 tall per CTA (9*14 = 126 exact)
#define TILE_H  14
#define Y_TILES 9
#define SM_W    132            // 128 cols + 4 pad floats
#define SM_H    16             // TILE_H + KH - 1
#define THREADS 256
#define STAGES  3
#define KER_ELEMS (C_IN * KH * KW)   // 576

#define STAGE_ELEMS (SM_H * SM_W)    // 2112 floats = 8448 B
#define CHUNKS_PER_ROW 32            // 32 * 4 floats = 128 cols, exact
#define TOTAL_CHUNKS   (SM_H * CHUNKS_PER_ROW)   // 512 -> exactly 2 per thread
#define CHUNK_ITERS    2

__device__ __forceinline__ uint32_t smem_u32(const void* p) {
    uint32_t a;
    asm("{ .reg .u64 t; cvta.to.shared.u64 t, %1; cvt.u32.u64 %0, t; }" : "=r"(a) : "l"(p));
    return a;
}
__device__ __forceinline__ void cp_async16(uint32_t smem_addr, const void* gptr) {
    asm volatile("cp.async.cg.shared.global [%0], [%1], 16;\n" :: "r"(smem_addr), "l"(gptr));
}
__device__ __forceinline__ void cp_commit() {
    asm volatile("cp.async.commit_group;\n" ::: "memory");
}
__device__ __forceinline__ void cp_wait_2() {
    asm volatile("cp.async.wait_group 2;\n" ::: "memory");
}

// Compute NR output rows (NR+2 input rows) for 2 columns at colp.
template<int NR>
__device__ __forceinline__ void conv_rows(const float* colp, const float* wp,
                                          float acc[][2])
{
    const float w0 = wp[0], w1 = wp[1], w2 = wp[2];
    const float w3 = wp[3], w4 = wp[4], w5 = wp[5];
    const float w6 = wp[6], w7 = wp[7], w8 = wp[8];
#pragma unroll
    for (int r = 0; r < NR + 2; ++r) {
        float2 fa = *(const float2*)(colp + r * SM_W);       // cols 0,1 (8B aligned)
        float2 fb = *(const float2*)(colp + r * SM_W + 2);   // cols 2,3
        float x0 = fa.x, x1 = fa.y, x2 = fb.x, x3 = fb.y;
#pragma unroll
        for (int o = 0; o < NR; ++o) {
            int ky = r - o;
            if (ky >= 0 && ky < KH) {
                float wa = (ky == 0) ? w0 : (ky == 1) ? w3 : w6;
                float wb = (ky == 0) ? w1 : (ky == 1) ? w4 : w7;
                float wc = (ky == 0) ? w2 : (ky == 1) ? w5 : w8;
                acc[o][0] = fmaf(x0, wa, fmaf(x1, wb, fmaf(x2, wc, acc[o][0])));
                acc[o][1] = fmaf(x1, wa, fmaf(x2, wb, fmaf(x3, wc, acc[o][1])));
            }
        }
    }
}

__global__ __launch_bounds__(THREADS, 4)
void imagewise_conv2d_kernel(const float* __restrict__ images,
                             const float* __restrict__ kernels,
                             float* __restrict__ out)
{
    __shared__ float s_img[STAGES][STAGE_ELEMS];  // 3 * 8448 = 25344 B
    __shared__ float s_ker[KER_ELEMS];            // 2304 B   -> 27648 B total

    const int tid = threadIdx.x;
    const int n   = blockIdx.y;            // image index
    const int y0  = blockIdx.x * TILE_H;   // first output row of this stripe

    // Stage this sample's full kernel stack once
    for (int i = tid; i < KER_ELEMS; i += THREADS) {
        s_ker[i] = kernels[n * KER_ELEMS + i];
    }

    const float* img_n = images + (size_t)n * C_IN * H_IN * W_IN;

    // ---- Per-thread cp.async chunk addresses (channel-invariant, no clamps) ----
    // y0 <= 112 and row <= 15 -> gy <= 127: always in bounds.
    int      g_off[CHUNK_ITERS];
    uint32_t s_off[CHUNK_ITERS];
#pragma unroll
    for (int it = 0; it < CHUNK_ITERS; ++it) {
        int j   = tid + it * THREADS;
        int row = j >> 5;           // j / 32
        int k   = j & 31;
        g_off[it] = (y0 + row) * W_IN + 4 * k;
        s_off[it] = (uint32_t)((row * SM_W + 4 * k) * sizeof(float));
    }
    uint32_t s_base[STAGES];
#pragma unroll
    for (int s = 0; s < STAGES; ++s) s_base[s] = smem_u32(&s_img[s][0]);

    // ---- Compute mapping: 2 cols x {4,4,4,2} rows per thread ----
    const int tx   = tid & 63;       // col group: cols 2tx, 2tx+1
    const int tyg  = tid >> 6;       // row group (warp-uniform)
    const int col0 = 2 * tx;
    const int row0 = 4 * tyg;        // rows {0-3, 4-7, 8-11, 12-13}

    float acc[4][2];
#pragma unroll
    for (int o = 0; o < 4; ++o) { acc[o][0] = 0.0f; acc[o][1] = 0.0f; }

    // ---- Prologue: prefetch channels 0 and 1 ----
#pragma unroll
    for (int s = 0; s < STAGES - 1; ++s) {
        const float* img_c = img_n + (size_t)s * H_IN * W_IN;
#pragma unroll
        for (int it = 0; it < CHUNK_ITERS; ++it)
            cp_async16(s_base[s] + s_off[it], img_c + g_off[it]);
        cp_commit();
    }

    // ---- Main loop: depth-3 pipeline, R15-proven barrier order ----
    int cur = 0;   // buffer holding channel c
    for (int c = 0; c < C_IN; ++c) {
        __syncthreads();   // all warps done reading buf[(c+2)%3] (compute c-1)

        // Issue channel c+2 into buffer (c+2)%3 == (cur+2)%3
        {
            int cn  = c + 2;
            int tgt = (cur + 2 >= STAGES) ? (cur - 1) : (cur + 2);
            if (cn < C_IN) {
                const float* img_c = img_n + (size_t)cn * H_IN * W_IN;
#pragma unroll
                for (int it = 0; it < CHUNK_ITERS; ++it)
                    cp_async16(s_base[tgt] + s_off[it], img_c + g_off[it]);
            }
            cp_commit();   // empty tail groups keep wait_group counts aligned
        }

        cp_wait_2();       // <=2 groups in flight -> channel c's group complete
        __syncthreads();   // publish stage c to all warps

        const float* buf = s_img[cur];
        const float* wp  = s_ker + c * 9;
        const float* colp = buf + row0 * SM_W + col0;

        if (tyg < 3) conv_rows<4>(colp, wp, acc);   // warp-uniform branch
        else         conv_rows<2>(colp, wp, acc);

        cur = (cur == STAGES - 1) ? 0 : cur + 1;
    }

    // ---- Store valid outputs (float2; tiles cover OH exactly, no gy guard) ----
    if (col0 <= OW - 2) {            // tx == 63 -> cols 126,127 out of range
        float* out_n = out + (size_t)n * OH * OW;
        const int nr = (tyg < 3) ? 4 : 2;
#pragma unroll
        for (int o = 0; o < 4; ++o) {
            if (o < nr) {
                int gy = y0 + row0 + o;
                *(float2*)(out_n + gy * OW + col0) = make_float2(acc[o][0], acc[o][1]);
            }
        }
    }
}

extern "C" void kernel_launch(void* const* d_in, const int* in_sizes, int n_in,
                              void* d_out, int out_size)
{
    const float* images  = (const float*)d_in[0];
    const float* kernels = (const float*)d_in[1];
    float* out = (float*)d_out;

    dim3 grid(Y_TILES, N_IMG);   // 9 x 64 = 576 CTAs (132 SMs x4 + 16 x3)
    imagewise_conv2d_kernel<<<grid, THREADS>>>(images, kernels, out);
}